// round 11
// baseline (speedup 1.0000x reference)
#include <cuda_runtime.h>
#include <cuda_bf16.h>

// Problem constants (fixed shapes from setup_inputs)
#define B_DIM 8
#define T_DIM 4096
#define D_DIM 1024
#define K_FFT 64
#define F_DIM (K_FFT / 2 + 1)        // 33

#define NUM_CONV 128                 // B * D/64
#define NTHREADS 512                 // 16 warps/SM: latency hiding for LDS/FMA chains

// ---------------------------------------------------------------------------
// Conv kernel: per-(batch, 64-channel tile) filter build + register-resident
// circular convolution of the last K_FFT timesteps.
// 512 threads: each thread owns (channel dl, 8 timesteps). Filter built via
// Chebyshev recurrence (FFMA-only). fr[64] register rotation keeps the inner
// 64x8 loop at pure compile-time-indexed FFMA.
// ---------------------------------------------------------------------------
__global__ void __launch_bounds__(NTHREADS, 1) spectral_conv_kernel(
    const float* __restrict__ x, const float* __restrict__ mask,
    const float* __restrict__ mix_w, float* __restrict__ out)
{
    __shared__ float gs_sh[64 * F_DIM];       // weighted sigmoid(mask) [dl][f]
    __shared__ float tab[K_FFT];              // a[n] = cos(pi n / 32)
    __shared__ float mw_sh[64];               // mix_w/64 tile
    __shared__ float w_sh[K_FFT * 64];        // window [k][dl]
    __shared__ float f_sh[64 * (K_FFT + 1)];  // filter [dl][n], pad 65

    const int bid = blockIdx.x;
    const int tid = threadIdx.x;

    const int b  = bid >> 4;          // 0..7
    const int d0 = (bid & 15) * 64;   // channel tile base

    // Stage the last-64-timestep window (coalesced), 8 elems/thread.
    const float* xb = x + ((long long)b * T_DIM + (T_DIM - K_FFT)) * D_DIM + d0;
    #pragma unroll
    for (int i = 0; i < 8; i++) {
        int idx = tid + i * NTHREADS;
        int k = idx >> 6, dl = idx & 63;
        w_sh[idx] = xb[(long long)k * D_DIM + dl];
    }

    // Stage sigmoid(mask) with DFT weights folded in:
    //   gs[dl][0] = g0, gs[dl][f] = 2*g_f (f=1..31), gs[dl][32] = g32
    const float* mrow = mask + (long long)d0 * F_DIM;
    for (int idx = tid; idx < 64 * F_DIM; idx += NTHREADS) {
        int f = idx % F_DIM;
        float g = 1.0f / (1.0f + expf(-mrow[idx]));
        float wgt = (f == 0 || f == 32) ? 1.0f : 2.0f;
        gs_sh[idx] = wgt * g;
    }
    if (tid < K_FFT)
        tab[tid] = cospif((float)tid * (1.0f / 32.0f));   // exact a[n]
    if (tid < 64)
        mw_sh[tid] = mix_w[d0 + tid] * (1.0f / 64.0f);
    __syncthreads();

    // Build filter via Chebyshev recurrence, 8 values/thread:
    //   f[dl][n] = (mix_w/64)*( gs0 + sum_{f=1..31} gs_f c_f(n) + gs32 c_32(n) )
    #pragma unroll
    for (int i = 0; i < 8; i++) {
        int idx = tid + i * NTHREADS;
        int dl = idx >> 6, n = idx & 63;
        const float* gd = gs_sh + dl * F_DIM;   // warp-uniform broadcast reads
        float a  = tab[n];
        float a2 = a + a;
        float cp = 1.0f, c = a;
        float s = gd[0];
        #pragma unroll
        for (int f = 1; f < 32; f++) {
            s = fmaf(gd[f], c, s);
            float cn = fmaf(a2, c, -cp);
            cp = c; c = cn;
        }
        s = fmaf(gd[32], c, s);                 // c == cos(pi n) = (-1)^n
        f_sh[dl * 65 + n] = s * mw_sh[dl];
    }
    __syncthreads();

    const int dl = tid & 63;
    const int t0 = (tid >> 6) * 8;              // 8 t-groups of 8

    // Pre-rotated filter in registers: fr[i] = f[(t0+i)&63]
    //   -> y[t0+j] = sum_k w[k] * fr[(j-k)&63], all compile-time reg indices.
    float fr[K_FFT];
    #pragma unroll
    for (int i = 0; i < K_FFT; i++)
        fr[i] = f_sh[dl * 65 + ((t0 + i) & 63)];

    float acc[8];
    #pragma unroll
    for (int j = 0; j < 8; j++) acc[j] = 0.0f;

    // k-loop in chunks of 8: decouple the w LDS from the FMA chain.
    #pragma unroll
    for (int kc = 0; kc < K_FFT; kc += 8) {
        float wbuf[8];
        #pragma unroll
        for (int u = 0; u < 8; u++)
            wbuf[u] = w_sh[(kc + u) * 64 + dl];
        #pragma unroll
        for (int u = 0; u < 8; u++) {
            const int k = kc + u;
            #pragma unroll
            for (int j = 0; j < 8; j++)
                acc[j] += wbuf[u] * fr[(j - k + K_FFT) & 63];
        }
    }

    float* ob = out + ((long long)b * T_DIM + (T_DIM - K_FFT)) * D_DIM + d0;
    #pragma unroll
    for (int j = 0; j < 8; j++)
        ob[(long long)(t0 + j) * D_DIM + dl] = acc[j];
}

// ---------------------------------------------------------------------------
// Launch: single memset node (~7 TB/s driver fill) + conv kernel, serial on
// one stream. Two graph nodes.
// ---------------------------------------------------------------------------
extern "C" void kernel_launch(void* const* d_in, const int* in_sizes, int n_in,
                              void* d_out, int out_size)
{
    const float* x     = (const float*)d_in[0];   // (B, T, D) fp32
    const float* mask  = (const float*)d_in[1];   // (D, 33)   fp32
    const float* mix_w = (const float*)d_in[2];   // (D,)      fp32
    float* out = (float*)d_out;                   // (B, T, D) fp32

    // Zero the entire output via the driver's fill path (one memset node).
    cudaMemsetAsync(out, 0, (size_t)out_size * sizeof(float), 0);

    // Compute the last-64-timestep windows (stream-ordered after the memset).
    spectral_conv_kernel<<<NUM_CONV, NTHREADS>>>(x, mask, mix_w, out);
}

// round 12
// speedup vs baseline: 1.0645x; 1.0645x over previous
#include <cuda_runtime.h>
#include <cuda_bf16.h>

// Problem constants (fixed shapes from setup_inputs)
#define B_DIM 8
#define T_DIM 4096
#define D_DIM 1024
#define K_FFT 64
#define F_DIM (K_FFT / 2 + 1)        // 33

#define NUM_CONV 128                 // B * D/64
#define NTHREADS 512

// ---------------------------------------------------------------------------
// Conv kernel: per-(batch, 64-channel tile) filter build + register-resident
// circular convolution of the last K_FFT timesteps.
// Build mapping: each thread owns ONE channel (ch = tid>>3) and 8 n-values,
// so gd[f] is one LDS per f feeding 8 parallel Chebyshev recurrences (ILP 8).
// Conv mapping: each thread owns one channel (dl = tid&63) and 8 timesteps,
// with the rotated filter fr[64] in registers -> pure compile-time FFMA.
// ---------------------------------------------------------------------------
__global__ void __launch_bounds__(NTHREADS, 1) spectral_conv_kernel(
    const float* __restrict__ x, const float* __restrict__ mask,
    const float* __restrict__ mix_w, float* __restrict__ out)
{
    __shared__ float gs_sh[64 * F_DIM];       // weighted sigmoid(mask) [dl][f]
    __shared__ float tab[K_FFT];              // a[n] = cos(pi n / 32)
    __shared__ float mw_sh[64];               // mix_w/64 tile
    __shared__ float w_sh[K_FFT * 64];        // window [k][dl]
    __shared__ float f_sh[64 * (K_FFT + 1)];  // filter [dl][n], pad 65

    const int bid = blockIdx.x;
    const int tid = threadIdx.x;

    const int b  = bid >> 4;          // 0..7
    const int d0 = (bid & 15) * 64;   // channel tile base

    // Stage the last-64-timestep window (coalesced), 8 elems/thread.
    const float* xb = x + ((long long)b * T_DIM + (T_DIM - K_FFT)) * D_DIM + d0;
    #pragma unroll
    for (int i = 0; i < 8; i++) {
        int idx = tid + i * NTHREADS;
        int k = idx >> 6, dl = idx & 63;
        w_sh[idx] = xb[(long long)k * D_DIM + dl];
    }

    // Stage sigmoid(mask) with DFT weights folded in:
    //   gs[dl][0] = g0, gs[dl][f] = 2*g_f (f=1..31), gs[dl][32] = g32
    const float* mrow = mask + (long long)d0 * F_DIM;
    for (int idx = tid; idx < 64 * F_DIM; idx += NTHREADS) {
        int f = idx % F_DIM;
        float g = 1.0f / (1.0f + __expf(-mrow[idx]));
        gs_sh[idx] = (f == 0 || f == 32) ? g : (2.0f * g);
    }
    if (tid < K_FFT)
        tab[tid] = cospif((float)tid * (1.0f / 32.0f));   // exact a[n]
    if (tid < 64)
        mw_sh[tid] = mix_w[d0 + tid] * (1.0f / 64.0f);
    __syncthreads();

    // ---- Filter build: 8 parallel Chebyshev recurrences per thread ----
    {
        const int ch = tid >> 3;              // one channel per thread
        const int n0 = (tid & 7) * 8;         // 8 consecutive n-values
        const float* gd = gs_sh + ch * F_DIM; // 4 distinct addrs/warp -> no conflict

        float a2[8], c[8], cp[8], s[8];
        const float g0 = gd[0];
        #pragma unroll
        for (int i = 0; i < 8; i++) {
            float a = tab[n0 + i];
            a2[i] = a + a;
            cp[i] = 1.0f;
            c[i]  = a;
            s[i]  = g0;
        }
        #pragma unroll
        for (int f = 1; f < 32; f++) {
            const float gf = gd[f];           // one LDS feeds 8 FMA chains
            #pragma unroll
            for (int i = 0; i < 8; i++) {
                s[i] = fmaf(gf, c[i], s[i]);
                float cn = fmaf(a2[i], c[i], -cp[i]);
                cp[i] = c[i];
                c[i]  = cn;
            }
        }
        const float g32 = gd[32];
        const float mw  = mw_sh[ch];
        #pragma unroll
        for (int i = 0; i < 8; i++)
            f_sh[ch * 65 + n0 + i] = fmaf(g32, c[i], s[i]) * mw;
    }
    __syncthreads();

    // ---- Circular convolution ----
    const int dl = tid & 63;
    const int t0 = (tid >> 6) * 8;            // 8 t-groups of 8

    // Pre-rotated filter in registers: fr[i] = f[(t0+i)&63]
    //   -> y[t0+j] = sum_k w[k] * fr[(j-k)&63], all compile-time reg indices.
    float fr[K_FFT];
    #pragma unroll
    for (int i = 0; i < K_FFT; i++)
        fr[i] = f_sh[dl * 65 + ((t0 + i) & 63)];

    float acc[8];
    #pragma unroll
    for (int j = 0; j < 8; j++) acc[j] = 0.0f;

    // k-loop in chunks of 8: decouple the w LDS from the FMA chain.
    #pragma unroll
    for (int kc = 0; kc < K_FFT; kc += 8) {
        float wbuf[8];
        #pragma unroll
        for (int u = 0; u < 8; u++)
            wbuf[u] = w_sh[(kc + u) * 64 + dl];
        #pragma unroll
        for (int u = 0; u < 8; u++) {
            const int k = kc + u;
            #pragma unroll
            for (int j = 0; j < 8; j++)
                acc[j] += wbuf[u] * fr[(j - k + K_FFT) & 63];
        }
    }

    float* ob = out + ((long long)b * T_DIM + (T_DIM - K_FFT)) * D_DIM + d0;
    #pragma unroll
    for (int j = 0; j < 8; j++)
        ob[(long long)(t0 + j) * D_DIM + dl] = acc[j];
}

// ---------------------------------------------------------------------------
// Launch: single memset node (~7 TB/s driver fill) + conv kernel, serial on
// one stream. Two graph nodes.
// ---------------------------------------------------------------------------
extern "C" void kernel_launch(void* const* d_in, const int* in_sizes, int n_in,
                              void* d_out, int out_size)
{
    const float* x     = (const float*)d_in[0];   // (B, T, D) fp32
    const float* mask  = (const float*)d_in[1];   // (D, 33)   fp32
    const float* mix_w = (const float*)d_in[2];   // (D,)      fp32
    float* out = (float*)d_out;                   // (B, T, D) fp32

    // Zero the entire output via the driver's fill path (one memset node).
    cudaMemsetAsync(out, 0, (size_t)out_size * sizeof(float), 0);

    // Compute the last-64-timestep windows (stream-ordered after the memset).
    spectral_conv_kernel<<<NUM_CONV, NTHREADS>>>(x, mask, mix_w, out);
}